// round 16
// baseline (speedup 1.0000x reference)
#include <cuda_runtime.h>

// Problem constants (B=64, S=512, H=768, W=MAX_WORD_LEN=256, VOCAB=50000, WE=300)
constexpr int B   = 64;
constexpr int S   = 512;
constexpr int H   = 768;
constexpr int W   = 256;
constexpr int WE  = 300;

constexpr int H4   = H  / 4;       // 192 float4 per transformer row
constexpr int WE4  = WE / 4;       // 75  float4 per w2v row
constexpr int OUT4 = H4 + WE4;     // 267 float4 per output row

constexpr int CH   = 3;            // H-part chunks per half-row warp (192/32/2)

// ---------------------------------------------------------------------------
// Warp-cooperative lower_bound over a sorted 512-int row.
// tv1 = trow[16*lane] must be preloaded (shared by all calls).
// ---------------------------------------------------------------------------
__device__ __forceinline__ int warp_lower_bound(const int* __restrict__ trow,
                                                int tv1, int target, int lane)
{
    const unsigned m1 = __ballot_sync(0xffffffffu, tv1 < target);
    const int nlt = __popc(m1);          // sampled points with value < target
    if (nlt == 0) return 0;              // trow[0] >= target
    const int base = 16 * (nlt - 1) + 1; // answer in [base, base+15] (or S)
    const int idx  = base + lane;
    const int v    = (lane < 16 && idx < S) ? trow[idx] : 0x7fffffff;
    const unsigned m2 = __ballot_sync(0xffffffffu, v < target);
    return base + __popc(m2);
}

// ---------------------------------------------------------------------------
// Single fused kernel. Each warp owns ONE HALF (h in {0,1}) of TWO
// consecutive output rows (words w0, w0+1) — the R14 layout with the per-warp
// fixed overhead amortized over 2x the streaming work:
//   * one tv1 sample + 3 lower_bounds per 2 words (shared middle boundary)
//   * both words' w2v gathers issued load->store up front (transient regs)
//   * the two mean loops walk ONE contiguous token range [s0, s2)
// Loop-live state stays acc[3]+v[3] -> fits the 42-reg cap of (256, 6).
// ---------------------------------------------------------------------------
__global__ void __launch_bounds__(256, 6)
embeddings_fused_kernel(const float4* __restrict__ hidden,     // [B, S, H4]
                        const float4* __restrict__ w2v,        // [VOCAB, WE4]
                        const int*    __restrict__ token_ids,  // [B, S]
                        const int*    __restrict__ word_ids,   // [B, W]
                        float4*       __restrict__ out)        // [B, W, OUT4]
{
    const int gwarp = (blockIdx.x << 3) | (threadIdx.x >> 5); // 0 .. B*W-1
    const int lane  = threadIdx.x & 31;
    const int pair  = gwarp >> 1;            // word-pair index (b*128 + wp)
    const int h     = gwarp & 1;             // half: 0 or 1
    const int b     = pair >> 7;             // / 128 pairs per batch
    const int w0    = (pair & 127) << 1;     // first word of the pair

    const int row0 = b * W + w0;
    float4* __restrict__ orow0 = out + (size_t)row0 * OUT4;
    float4* __restrict__ orow1 = orow0 + OUT4;

    // --- w2v gathers for BOTH words: load -> store immediately -------------
    {
        const int wid0 = word_ids[row0];
        const int wid1 = word_ids[row0 + 1];
        const float4* __restrict__ g0 = w2v + (size_t)wid0 * WE4;
        const float4* __restrict__ g1 = w2v + (size_t)wid1 * WE4;
        int gj0, gj1;
        if (h == 0) { gj0 = lane;      gj1 = lane + 32; }   // chunks 0,1
        else        { gj0 = lane + 64; gj1 = WE4;       }   // chunk 2 (11 lanes)
        if (gj0 < WE4) {
            __stcs(orow0 + H4 + gj0, __ldg(g0 + gj0));
            __stcs(orow1 + H4 + gj0, __ldg(g1 + gj0));
        }
        if (gj1 < WE4) {
            __stcs(orow0 + H4 + gj1, __ldg(g0 + gj1));
            __stcs(orow1 + H4 + gj1, __ldg(g1 + gj1));
        }
    }

    // --- warp-cooperative bounds: 3 searches cover both words --------------
    const int* __restrict__ trow = token_ids + b * S;
    const int tv1 = trow[lane << 4];         // sample trow[16*lane]
    const int s0  = warp_lower_bound(trow, tv1, w0,     lane);
    const int s1  = warp_lower_bound(trow, tv1, w0 + 1, lane);
    const int s2  = warp_lower_bound(trow, tv1, w0 + 2, lane);
    const int count0 = s1 - s0;
    const int count1 = s2 - s1;
    const float inv0 = (count0 > 0) ? (1.0f / (float)count0) : 0.0f;
    const float inv1 = (count1 > 0) ? (1.0f / (float)count1) : 0.0f;

    // --- mean loops: one contiguous stream [s0, s2), 3 loads per token -----
    const int col0 = lane + 32 * (CH * h);   // this warp's first column chunk
    const float4* p = hidden + ((size_t)b * S + s0) * H4 + col0;

    float4 acc[CH];
    #pragma unroll
    for (int c = 0; c < CH; ++c) acc[c] = make_float4(0.f, 0.f, 0.f, 0.f);

    for (int t = 0; t < count0; ++t, p += H4) {
        float4 v[CH];
        #pragma unroll
        for (int c = 0; c < CH; ++c) v[c] = __ldcs(p + 32 * c);
        #pragma unroll
        for (int c = 0; c < CH; ++c) {
            acc[c].x += v[c].x; acc[c].y += v[c].y;
            acc[c].z += v[c].z; acc[c].w += v[c].w;
        }
    }
    #pragma unroll
    for (int c = 0; c < CH; ++c) {
        float4 r;
        r.x = acc[c].x * inv0; r.y = acc[c].y * inv0;
        r.z = acc[c].z * inv0; r.w = acc[c].w * inv0;
        __stcs(orow0 + col0 + 32 * c, r);
        acc[c] = make_float4(0.f, 0.f, 0.f, 0.f);
    }

    for (int t = 0; t < count1; ++t, p += H4) {
        float4 v[CH];
        #pragma unroll
        for (int c = 0; c < CH; ++c) v[c] = __ldcs(p + 32 * c);
        #pragma unroll
        for (int c = 0; c < CH; ++c) {
            acc[c].x += v[c].x; acc[c].y += v[c].y;
            acc[c].z += v[c].z; acc[c].w += v[c].w;
        }
    }
    #pragma unroll
    for (int c = 0; c < CH; ++c) {
        float4 r;
        r.x = acc[c].x * inv1; r.y = acc[c].y * inv1;
        r.z = acc[c].z * inv1; r.w = acc[c].w * inv1;
        __stcs(orow1 + col0 + 32 * c, r);
    }
}

extern "C" void kernel_launch(void* const* d_in, const int* in_sizes, int n_in,
                              void* d_out, int out_size)
{
    const float4* hidden    = (const float4*)d_in[0];   // [B,S,H] f32
    const float4* w2v       = (const float4*)d_in[1];   // [VOCAB,WE] f32
    const int*    token_ids = (const int*)d_in[2];      // [B,S]
    const int*    word_ids  = (const int*)d_in[3];      // [B,W]
    float4*       out       = (float4*)d_out;           // [B,W,H+WE] f32

    // 2 warps per word-pair, 8 warps per CTA -> B*W/8 = 2048 CTAs
    embeddings_fused_kernel<<<(B * W) / 8, 256>>>(hidden, w2v, token_ids,
                                                  word_ids, out);
}